// round 1
// baseline (speedup 1.0000x reference)
#include <cuda_runtime.h>
#include <cstdint>
#include <cfloat>

// Problem constants (fixed by the reference)
#define BB 8192
#define CC 64
#define KK 256
#define DD 64
#define N1 (BB*CC)           // 524288  (codes / mse element count)
#define NCENT (CC*KK*DD)     // 1048576 (centroids passthrough)
#define BT 64                // b-rows per block
#define NBT (BB/BT)          // 128 b-tiles

// -------- scratch (static device arrays; no allocations allowed) --------
__device__ float  g_maxv[N1];
__device__ int    g_maxi[N1];
__device__ float  g_minv[N1];
__device__ int    g_mini[N1];
__device__ float2 g_part[CC*NBT];   // per-(c, btile) partial (sum, sumsq)
__device__ float  g_mean[CC];
__device__ float  g_invstd[CC];

// Packed fp32x2 FMA — required for full 128-FMA/cyc/SM fp32 rate on Blackwell.
__device__ __forceinline__ void ffma2(unsigned long long &d,
                                      unsigned long long a,
                                      unsigned long long b) {
    asm("fma.rn.f32x2 %0, %1, %2, %0;" : "+l"(d) : "l"(a), "l"(b));
}

#define SMEM_X_BYTES (BT*DD*sizeof(float2))        // 32768: x duplicated (x,x)
#define SMEM_C_BYTES (DD*KK*sizeof(float))         // 65536: centroids, d-major
#define SMEM_BYTES   (SMEM_X_BYTES + SMEM_C_BYTES) // 98304

// ---------------------------------------------------------------------------
// Pass 1: fused GEMM (x[b,c,:] . cent[c,k,:]) + per-(b,c) max/argmax/min/argmin
//         + per-channel partial sums for BatchNorm stats. r is never stored.
// grid = (NBT, CC), block = 256 threads. Thread tile = 8b x 8k (k packed x2).
// ---------------------------------------------------------------------------
__global__ __launch_bounds__(256, 2)
void pass1_kernel(const float* __restrict__ x, const float* __restrict__ cent) {
    extern __shared__ char sm[];
    float2* xs2 = (float2*)sm;                       // [BT][DD]  duplicated pairs
    float*  csf = (float*)(sm + SMEM_X_BYTES);       // [DD][KK]  d-major

    const int tid = threadIdx.x;
    const int c   = blockIdx.y;
    const int b0  = blockIdx.x * BT;

    // ---- load x tile (BT x DD), duplicate each scalar into (x,x) ----
    {
        const float4* xg = (const float4*)x + ((size_t)b0*CC + c)*(DD/4);
        #pragma unroll
        for (int i = 0; i < 4; ++i) {
            int f = i*256 + tid;            // 1024 float4 total
            int row = f >> 4, q = f & 15;   // 16 float4 per row (coalesced)
            float4 v = xg[(size_t)row*(CC*DD/4) + q];
            int base = row*DD + q*4;
            xs2[base+0] = make_float2(v.x, v.x);
            xs2[base+1] = make_float2(v.y, v.y);
            xs2[base+2] = make_float2(v.z, v.z);
            xs2[base+3] = make_float2(v.w, v.w);
        }
    }
    // ---- load centroids: thread tid owns row k=tid; transposed store is
    //      conflict-free (lanes write consecutive floats csf[d][k=tid]) ----
    {
        const float4* cg = (const float4*)cent + ((size_t)c*KK + tid)*(DD/4);
        #pragma unroll
        for (int q = 0; q < 16; ++q) {
            float4 v = cg[q];
            int d0 = q*4;
            csf[(d0+0)*KK + tid] = v.x;
            csf[(d0+1)*KK + tid] = v.y;
            csf[(d0+2)*KK + tid] = v.z;
            csf[(d0+3)*KK + tid] = v.w;
        }
    }
    __syncthreads();

    const int txk = tid & 31;   // lane: k position
    const int tyb = tid >> 5;   // warp: b group (warp covers full K for its 8 b)

    // 8 b-rows x 4 k-pairs (= 8 k) of packed f32x2 accumulators
    unsigned long long acc[8][4];
    #pragma unroll
    for (int j = 0; j < 8; ++j)
        #pragma unroll
        for (int p = 0; p < 4; ++p) acc[j][p] = 0ull;

    const ulonglong2* cs2 = (const ulonglong2*)csf;  // row = 64 x ulonglong2

    #pragma unroll 4
    for (int dd = 0; dd < DD; dd += 2) {
        ulonglong2 cA0 = cs2[ dd   *(KK/4) + txk];        // k = 4t..4t+3
        ulonglong2 cB0 = cs2[ dd   *(KK/4) + 32 + txk];   // k = 128+4t..
        ulonglong2 cA1 = cs2[(dd+1)*(KK/4) + txk];
        ulonglong2 cB1 = cs2[(dd+1)*(KK/4) + 32 + txk];
        #pragma unroll
        for (int j = 0; j < 8; ++j) {
            // (x_d,x_d, x_{d+1},x_{d+1}) in one broadcast LDS.128
            ulonglong2 xv = *(const ulonglong2*)&xs2[(tyb*8 + j)*DD + dd];
            ffma2(acc[j][0], xv.x, cA0.x);
            ffma2(acc[j][1], xv.x, cA0.y);
            ffma2(acc[j][2], xv.x, cB0.x);
            ffma2(acc[j][3], xv.x, cB0.y);
            ffma2(acc[j][0], xv.y, cA1.x);
            ffma2(acc[j][1], xv.y, cA1.y);
            ffma2(acc[j][2], xv.y, cB1.x);
            ffma2(acc[j][3], xv.y, cB1.y);
        }
    }

    // ---- epilogue: per-b max/argmax + min/argmin over k, channel sums ----
    float sum = 0.f, sum2 = 0.f;
    const int kb = txk * 4;
    #pragma unroll
    for (int j = 0; j < 8; ++j) {
        float bmaxv = -FLT_MAX, bminv = FLT_MAX;
        int   bmaxi = 0,        bmini = 0;
        #pragma unroll
        for (int p = 0; p < 4; ++p) {
            float2 v = *(float2*)&acc[j][p];
            int k0 = (p < 2) ? (kb + 2*p) : (128 + kb + 2*(p-2));
            sum  += v.x + v.y;
            sum2 += v.x*v.x + v.y*v.y;
            // ascending k + strict compare => first-occurrence semantics
            if (v.x > bmaxv) { bmaxv = v.x; bmaxi = k0;   }
            if (v.y > bmaxv) { bmaxv = v.y; bmaxi = k0+1; }
            if (v.x < bminv) { bminv = v.x; bmini = k0;   }
            if (v.y < bminv) { bminv = v.y; bmini = k0+1; }
        }
        // warp butterfly reduce (lanes of this warp cover all 256 k)
        #pragma unroll
        for (int off = 16; off > 0; off >>= 1) {
            float mv = __shfl_xor_sync(0xffffffffu, bmaxv, off);
            int   mi = __shfl_xor_sync(0xffffffffu, bmaxi, off);
            if (mv > bmaxv || (mv == bmaxv && mi < bmaxi)) { bmaxv = mv; bmaxi = mi; }
            float nv = __shfl_xor_sync(0xffffffffu, bminv, off);
            int   ni = __shfl_xor_sync(0xffffffffu, bmini, off);
            if (nv < bminv || (nv == bminv && ni < bmini)) { bminv = nv; bmini = ni; }
        }
        if (txk == 0) {
            size_t o = (size_t)(b0 + tyb*8 + j)*CC + c;
            g_maxv[o] = bmaxv; g_maxi[o] = bmaxi;
            g_minv[o] = bminv; g_mini[o] = bmini;
        }
    }

    // deterministic per-block partial sums (no float atomics)
    #pragma unroll
    for (int off = 16; off > 0; off >>= 1) {
        sum  += __shfl_xor_sync(0xffffffffu, sum,  off);
        sum2 += __shfl_xor_sync(0xffffffffu, sum2, off);
    }
    __shared__ float2 red[8];
    if (txk == 0) red[tyb] = make_float2(sum, sum2);
    __syncthreads();
    if (tid == 0) {
        float s = 0.f, s2 = 0.f;
        #pragma unroll
        for (int w = 0; w < 8; ++w) { s += red[w].x; s2 += red[w].y; }
        g_part[(size_t)c*NBT + blockIdx.x] = make_float2(s, s2);
    }
}

// ---------------------------------------------------------------------------
// Pass 2: reduce 128 partials per channel -> mean, invstd (tiny, deterministic)
// ---------------------------------------------------------------------------
__global__ void pass2_kernel() {
    int c = threadIdx.x;
    if (c < CC) {
        double s = 0.0, s2 = 0.0;
        for (int i = 0; i < NBT; ++i) {
            float2 p = g_part[(size_t)c*NBT + i];
            s += (double)p.x; s2 += (double)p.y;
        }
        const double cnt = (double)BB * (double)KK;
        double mean = s / cnt;
        double var  = s2 / cnt - mean*mean;
        g_mean[c]   = (float)mean;
        g_invstd[c] = rsqrtf((float)var + 1e-5f);
    }
}

// ---------------------------------------------------------------------------
// Pass 3: codes + mse. BN is monotone per channel:
//   gamma>0 -> argmax(raw), gamma<0 -> argmin(raw), gamma==0 -> index 0.
// Output layout: [codes (B*C) | mse (B*C) | centroids (C*K*D)] as float32.
// ---------------------------------------------------------------------------
__global__ void pass3_kernel(const float* __restrict__ gamma,
                             const float* __restrict__ beta,
                             float* __restrict__ out) {
    int idx = blockIdx.x*blockDim.x + threadIdx.x;
    if (idx >= N1) return;
    int c = idx & (CC-1);
    float g  = gamma[c], be = beta[c];
    float m  = g_mean[c], is = g_invstd[c];
    float code, val;
    if (g > 0.f)      { code = (float)g_maxi[idx]; val = (g_maxv[idx]-m)*is*g + be; }
    else if (g < 0.f) { code = (float)g_mini[idx]; val = (g_minv[idx]-m)*is*g + be; }
    else              { code = 0.f;                val = be; }
    out[idx]      = code;
    out[N1 + idx] = val;
}

// Pass 4: centroids passthrough (tie_in_n_out=True)
__global__ void pass4_kernel(const float4* __restrict__ cent,
                             float4* __restrict__ out) {
    int idx = blockIdx.x*blockDim.x + threadIdx.x;
    if (idx < NCENT/4) out[idx] = cent[idx];
}

// ---------------------------------------------------------------------------
extern "C" void kernel_launch(void* const* d_in, const int* in_sizes, int n_in,
                              void* d_out, int out_size) {
    (void)in_sizes; (void)n_in; (void)out_size;
    const float* x     = (const float*)d_in[0];  // (B, C, D)
    const float* cent  = (const float*)d_in[1];  // (C, K, D)
    const float* gamma = (const float*)d_in[2];  // (C,)
    const float* beta  = (const float*)d_in[3];  // (C,)
    float* out = (float*)d_out;

    cudaFuncSetAttribute(pass1_kernel,
                         cudaFuncAttributeMaxDynamicSharedMemorySize, SMEM_BYTES);

    pass1_kernel<<<dim3(NBT, CC), 256, SMEM_BYTES>>>(x, cent);
    pass2_kernel<<<1, 64>>>();
    pass3_kernel<<<(N1 + 255)/256, 256>>>(gamma, beta, out);
    pass4_kernel<<<(NCENT/4 + 255)/256, 256>>>((const float4*)cent,
                                               (float4*)(out + 2*(size_t)N1));
}

// round 5
// speedup vs baseline: 1.5797x; 1.5797x over previous
#include <cuda_runtime.h>
#include <cuda_bf16.h>
#include <cstdint>
#include <cfloat>

// Problem constants
#define BB 8192
#define CC 64
#define KK 256
#define DD 64
#define N1 (BB*CC)            // 524288
#define NCENT (CC*KK*DD)      // 1048576
#define TTILES 4
#define NGX 16                // BB / (128*TTILES)

// -------- static device scratch (no allocations allowed) --------
__device__ __align__(16) __nv_bfloat16 g_cb0[NCENT];   // h split, [c][k][d]
__device__ __align__(16) __nv_bfloat16 g_cb1[NCENT];   // m split
__device__ __align__(16) __nv_bfloat16 g_cb2[NCENT];   // l split
__device__ int    g_codei[N1];     // [c][b]
__device__ float  g_selv[N1];      // [c][b]
__device__ float2 g_part[CC*NGX];
__device__ float  g_mean[CC];
__device__ float  g_invstd[CC];

// ---------------- smem layout (dynamic) ----------------
#define SM_B      0u        // 3 splits x 32768  (256 rows x 128B, swizzled)
#define SM_A      98304u    // 3 splits x 16384  (128 rows x 128B, swizzled)
#define SM_CAND   147456u   // 128 rows x 2 warpN x float4
#define SM_RED    151552u   // 8 x float2
#define SM_TOTAL  151616u

#define SWZ(o) ((uint32_t)(o) ^ ((((uint32_t)(o))>>3)&0x70u))

// ---------------- PTX helpers (portable sm_80+ only) ----------------
static __device__ __forceinline__ uint32_t smem_u32(const void* p){
    uint32_t a;
    asm("{ .reg .u64 t; cvta.to.shared.u64 t, %1; cvt.u32.u64 %0, t; }"
        : "=r"(a) : "l"(p));
    return a;
}
static __device__ __forceinline__ void ldsm4(uint32_t* r, uint32_t addr){
    asm volatile("ldmatrix.sync.aligned.m8n8.x4.shared.b16 {%0,%1,%2,%3}, [%4];"
        : "=r"(r[0]), "=r"(r[1]), "=r"(r[2]), "=r"(r[3]) : "r"(addr));
}
static __device__ __forceinline__ void mma16816(float* c, const uint32_t* a,
                                                uint32_t b0, uint32_t b1){
    asm volatile(
        "mma.sync.aligned.m16n8k16.row.col.f32.bf16.bf16.f32 "
        "{%0,%1,%2,%3}, {%4,%5,%6,%7}, {%8,%9}, {%0,%1,%2,%3};"
        : "+f"(c[0]), "+f"(c[1]), "+f"(c[2]), "+f"(c[3])
        : "r"(a[0]), "r"(a[1]), "r"(a[2]), "r"(a[3]), "r"(b0), "r"(b1));
}

// ---------------- conversion helpers ----------------
static __device__ __forceinline__ void split3(float x, __nv_bfloat16& h,
                                              __nv_bfloat16& m, __nv_bfloat16& l){
    h = __float2bfloat16_rn(x);
    float r1 = x - __bfloat162float(h);
    m = __float2bfloat16_rn(r1);
    float r2 = r1 - __bfloat162float(m);
    l = __float2bfloat16_rn(r2);
}
static __device__ __forceinline__ uint32_t pk(__nv_bfloat16 a, __nv_bfloat16 b){
    __nv_bfloat162 t = __halves2bfloat162(a, b);
    return *reinterpret_cast<uint32_t*>(&t);
}

// convert one 128x64 fp32 A tile into 3 bf16 splits in smem (all 256 threads)
static __device__ __forceinline__ void convertA(char* sm, const float* __restrict__ x,
                                                int gx, int c, int t, int tid){
    const int b0 = (gx*TTILES + t)*128;
    #pragma unroll
    for (int i = 0; i < 4; ++i){
        int g = i*256 + tid;                 // 0..1023
        int row = g >> 3, q8 = g & 7;        // row 0..127
        const float4* xp = (const float4*)x + ((size_t)(b0+row)*CC + c)*(DD/4) + q8*2;
        float4 v0 = xp[0], v1 = xp[1];
        float f[8] = {v0.x,v0.y,v0.z,v0.w,v1.x,v1.y,v1.z,v1.w};
        uint32_t H[4], M[4], L[4];
        #pragma unroll
        for (int pi = 0; pi < 4; ++pi){
            __nv_bfloat16 h0,m0,l0,h1,m1,l1;
            split3(f[2*pi],   h0, m0, l0);
            split3(f[2*pi+1], h1, m1, l1);
            H[pi] = pk(h0,h1); M[pi] = pk(m0,m1); L[pi] = pk(l0,l1);
        }
        uint32_t so = SWZ(row*128 + q8*16);
        *(uint4*)(sm + SM_A + so)          = make_uint4(H[0],H[1],H[2],H[3]);
        *(uint4*)(sm + SM_A + 16384u + so) = make_uint4(M[0],M[1],M[2],M[3]);
        *(uint4*)(sm + SM_A + 32768u + so) = make_uint4(L[0],L[1],L[2],L[3]);
    }
}

// ---------------------------------------------------------------------------
// Main kernel: grid (NGX, CC), 256 threads, warp grid 4(m) x 2(n),
// warp tile 32x64, N in two 128-halves. 8-pass bf16 split GEMM on mma.sync.
// Split-pass pairs (A-split, B-split), only l*l dropped:
//   sb=2 (l): {m*l, h*l}   sb=1 (m): {l*m, m*m, h*m}   sb=0 (h): {l*h, m*h, h*h}
// ---------------------------------------------------------------------------
__global__ __launch_bounds__(256, 1)
void mma_kernel(const float* __restrict__ x, const float* __restrict__ gamma){
    extern __shared__ __align__(16) char sm[];
    const uint32_t smb = smem_u32(sm);
    const int tid = threadIdx.x, lane = tid & 31, wid = tid >> 5;
    const int warpM = wid >> 1, warpN = wid & 1, q = lane >> 2;
    const int gx = blockIdx.x, c = blockIdx.y;

    // ---- load 3 B splits into swizzled smem (96KB) ----
    {
        const uint4* cb0 = (const uint4*)g_cb0;
        const uint4* cb1 = (const uint4*)g_cb1;
        const uint4* cb2 = (const uint4*)g_cb2;
        #pragma unroll
        for (int i = 0; i < 24; ++i){
            int flat = i*256 + tid;          // 0..6143
            int s    = flat >> 11;
            int g    = flat & 2047;
            int row  = g >> 3, q8 = g & 7;
            const uint4* src = (s==0) ? cb0 : (s==1) ? cb1 : cb2;
            uint4 v = src[((size_t)c*KK + row)*8 + q8];
            *(uint4*)(sm + SM_B + (uint32_t)s*32768u + SWZ(row*128 + q8*16)) = v;
        }
    }

    const float gmm = gamma[c];
    float sum = 0.f, sum2 = 0.f;

    // per-lane ldmatrix address components
    const uint32_t aRow  = (uint32_t)(warpM*32 + (lane & 15));
    const uint32_t aCol  = (uint32_t)((lane >> 4) << 4);       // 0 or 16 bytes
    const uint32_t bRowL = (uint32_t)(((lane >> 4) << 3) + (lane & 7));
    const uint32_t bCol  = (uint32_t)((lane & 8) << 1);        // 0 or 16 bytes

    // 8-pass tables grouped by B split (low-magnitude first within each group)
    const int SBt[3] = {2, 1, 0};
    const int SAt[3][3] = {{1,0,-1},{2,1,0},{2,1,0}};

    float4* cand = (float4*)(sm + SM_CAND);

    for (int t = 0; t < TTILES; ++t){
        convertA(sm, x, gx, c, t, tid);
        __syncthreads();

        float rmax[4], rmin[4];
        int   rmaxi[4], rmini[4];
        #pragma unroll
        for (int s4 = 0; s4 < 4; ++s4){
            rmax[s4] = -FLT_MAX; rmin[s4] = FLT_MAX; rmaxi[s4] = 0; rmini[s4] = 0;
        }

        #pragma unroll
        for (int nh = 0; nh < 2; ++nh){
            float acc[2][8][4];
            #pragma unroll
            for (int mi = 0; mi < 2; ++mi)
                #pragma unroll
                for (int nj = 0; nj < 8; ++nj)
                    #pragma unroll
                    for (int e = 0; e < 4; ++e) acc[mi][nj][e] = 0.f;

            #pragma unroll
            for (int ks = 0; ks < 4; ++ks){
                // A fragments: all 3 splits x 2 m-tiles
                uint32_t aF[3][2][4];
                #pragma unroll
                for (int s = 0; s < 3; ++s)
                    #pragma unroll
                    for (int mi = 0; mi < 2; ++mi)
                        ldsm4(aF[s][mi], smb + SM_A + (uint32_t)s*16384u +
                              SWZ(aRow*128u + (uint32_t)mi*2048u +
                                  (uint32_t)ks*32u + aCol));
                // B splits on demand (16 regs live at a time)
                #pragma unroll
                for (int g3 = 0; g3 < 3; ++g3){
                    const int sb = SBt[g3];
                    uint32_t bF[4][4];
                    #pragma unroll
                    for (int njp = 0; njp < 4; ++njp)
                        ldsm4(bF[njp], smb + SM_B + (uint32_t)sb*32768u +
                              SWZ((uint32_t)(nh*128 + warpN*64 + njp*16 + bRowL)*128u +
                                  (uint32_t)ks*32u + bCol));
                    #pragma unroll
                    for (int pi = 0; pi < 3; ++pi){
                        const int sa = SAt[g3][pi];
                        if (sa < 0) continue;
                        #pragma unroll
                        for (int mi = 0; mi < 2; ++mi)
                            #pragma unroll
                            for (int njp = 0; njp < 4; ++njp){
                                mma16816(acc[mi][2*njp],   aF[sa][mi], bF[njp][0], bF[njp][1]);
                                mma16816(acc[mi][2*njp+1], aF[sa][mi], bF[njp][2], bF[njp][3]);
                            }
                    }
                }
            }

            // ---- epilogue scan ----
            const int kbase = nh*128 + warpN*64 + 2*(lane & 3);
            #pragma unroll
            for (int mi = 0; mi < 2; ++mi){
                #pragma unroll
                for (int nj = 0; nj < 8; ++nj){
                    const int k0 = kbase + nj*8;
                    float v0 = acc[mi][nj][0], v1 = acc[mi][nj][1];
                    float v2 = acc[mi][nj][2], v3 = acc[mi][nj][3];
                    sum += v0 + v1 + v2 + v3;
                    sum2 = fmaf(v0, v0, sum2); sum2 = fmaf(v1, v1, sum2);
                    sum2 = fmaf(v2, v2, sum2); sum2 = fmaf(v3, v3, sum2);
                    const int s0 = mi*2, s1 = mi*2 + 1;
                    if (v0 > rmax[s0]){ rmax[s0] = v0; rmaxi[s0] = k0;   }
                    if (v1 > rmax[s0]){ rmax[s0] = v1; rmaxi[s0] = k0+1; }
                    if (v0 < rmin[s0]){ rmin[s0] = v0; rmini[s0] = k0;   }
                    if (v1 < rmin[s0]){ rmin[s0] = v1; rmini[s0] = k0+1; }
                    if (v2 > rmax[s1]){ rmax[s1] = v2; rmaxi[s1] = k0;   }
                    if (v3 > rmax[s1]){ rmax[s1] = v3; rmaxi[s1] = k0+1; }
                    if (v2 < rmin[s1]){ rmin[s1] = v2; rmini[s1] = k0;   }
                    if (v3 < rmin[s1]){ rmin[s1] = v3; rmini[s1] = k0+1; }
                }
            }
        }

        // ---- cross-lane (quad) reduce, write candidates ----
        #pragma unroll
        for (int s4 = 0; s4 < 4; ++s4){
            float mv = rmax[s4]; int mi_ = rmaxi[s4];
            float nv = rmin[s4]; int ni_ = rmini[s4];
            #pragma unroll
            for (int off = 1; off <= 2; off <<= 1){
                float ov = __shfl_xor_sync(0xffffffffu, mv, off);
                int   oi = __shfl_xor_sync(0xffffffffu, mi_, off);
                if (ov > mv || (ov == mv && oi < mi_)){ mv = ov; mi_ = oi; }
                float pv = __shfl_xor_sync(0xffffffffu, nv, off);
                int   pi2 = __shfl_xor_sync(0xffffffffu, ni_, off);
                if (pv < nv || (pv == nv && pi2 < ni_)){ nv = pv; ni_ = pi2; }
            }
            if ((lane & 3) == 0){
                int row = warpM*32 + (s4 >> 1)*16 + (s4 & 1)*8 + q;
                cand[row*2 + warpN] = make_float4(mv, __int_as_float(mi_),
                                                  nv, __int_as_float(ni_));
            }
        }
        __syncthreads();

        // ---- merge across the two n-warps, write staged outputs ----
        if (tid < 128){
            float4 c0 = cand[tid*2 + 0], c1 = cand[tid*2 + 1];
            float mv = c0.x; int mi_ = __float_as_int(c0.y);
            int   oi = __float_as_int(c1.y);
            if (c1.x > mv || (c1.x == mv && oi < mi_)){ mv = c1.x; mi_ = oi; }
            float nv = c0.z; int ni_ = __float_as_int(c0.w);
            int   pi2 = __float_as_int(c1.w);
            if (c1.z < nv || (c1.z == nv && pi2 < ni_)){ nv = c1.z; ni_ = pi2; }
            const int b = (gx*TTILES + t)*128 + tid;
            int code; float sv;
            if      (gmm > 0.f){ code = mi_; sv = mv;  }
            else if (gmm < 0.f){ code = ni_; sv = nv;  }
            else               { code = 0;   sv = 0.f; }
            g_codei[(size_t)c*BB + b] = code;
            g_selv [(size_t)c*BB + b] = sv;
        }
        __syncthreads();
    }

    // ---- per-block stats partial (deterministic) ----
    #pragma unroll
    for (int off = 16; off; off >>= 1){
        sum  += __shfl_xor_sync(0xffffffffu, sum,  off);
        sum2 += __shfl_xor_sync(0xffffffffu, sum2, off);
    }
    float2* red = (float2*)(sm + SM_RED);
    if (lane == 0) red[wid] = make_float2(sum, sum2);
    __syncthreads();
    if (tid == 0){
        float s = 0.f, s2 = 0.f;
        #pragma unroll
        for (int w = 0; w < 8; ++w){ s += red[w].x; s2 += red[w].y; }
        g_part[c*NGX + gx] = make_float2(s, s2);
    }
}

// ---------------------------------------------------------------------------
// Prep: centroid bf16 3-way splits + centroids passthrough to out
// ---------------------------------------------------------------------------
__global__ void prep_kernel(const float4* __restrict__ cent,
                            float4* __restrict__ outc){
    int i = blockIdx.x*256 + threadIdx.x;    // < NCENT/4
    float4 v = cent[i];
    outc[i] = v;
    float f[4] = {v.x, v.y, v.z, v.w};
    __nv_bfloat16 h[4], m[4], l[4];
    #pragma unroll
    for (int p = 0; p < 4; ++p) split3(f[p], h[p], m[p], l[p]);
    ((uint2*)g_cb0)[i] = make_uint2(pk(h[0],h[1]), pk(h[2],h[3]));
    ((uint2*)g_cb1)[i] = make_uint2(pk(m[0],m[1]), pk(m[2],m[3]));
    ((uint2*)g_cb2)[i] = make_uint2(pk(l[0],l[1]), pk(l[2],l[3]));
}

// ---------------------------------------------------------------------------
// Stats reduce: 16 partials per channel -> mean, invstd
// ---------------------------------------------------------------------------
__global__ void pass2_kernel(){
    int c = threadIdx.x;
    if (c < CC){
        double s = 0.0, s2 = 0.0;
        for (int i = 0; i < NGX; ++i){
            float2 p = g_part[c*NGX + i];
            s += (double)p.x; s2 += (double)p.y;
        }
        const double cnt = (double)BB*(double)KK;
        double mean = s / cnt;
        double var  = s2 / cnt - mean*mean;
        g_mean[c]   = (float)mean;
        g_invstd[c] = rsqrtf((float)var + 1e-5f);
    }
}

// ---------------------------------------------------------------------------
// Finalize: normalize selected values, transpose [c][b] -> [b][c], write out
// ---------------------------------------------------------------------------
__global__ __launch_bounds__(256)
void pass3_kernel(const float* __restrict__ gamma, const float* __restrict__ beta,
                  float* __restrict__ out){
    __shared__ float tc[64][65];
    __shared__ float tv[64][65];
    const int tid = threadIdx.x;
    const int b0  = blockIdx.x*64;
    #pragma unroll
    for (int i = 0; i < 16; ++i){
        int flat = i*256 + tid;
        int cc = flat >> 6, bq = flat & 63;
        int b  = b0 + bq;
        float g = gamma[cc];
        int  code = g_codei[(size_t)cc*BB + b];
        float val;
        if (g != 0.f)
            val = (g_selv[(size_t)cc*BB + b] - g_mean[cc])*g_invstd[cc]*g + beta[cc];
        else
            val = beta[cc];
        tc[bq][cc] = (float)code;
        tv[bq][cc] = val;
    }
    __syncthreads();
    #pragma unroll
    for (int i = 0; i < 16; ++i){
        int flat = i*256 + tid;
        int row = flat >> 6, cc = flat & 63;
        size_t o = (size_t)(b0 + row)*CC + cc;
        out[o]      = tc[row][cc];
        out[N1 + o] = tv[row][cc];
    }
}

// ---------------------------------------------------------------------------
extern "C" void kernel_launch(void* const* d_in, const int* in_sizes, int n_in,
                              void* d_out, int out_size){
    (void)in_sizes; (void)n_in; (void)out_size;
    const float* x     = (const float*)d_in[0];
    const float* cent  = (const float*)d_in[1];
    const float* gamma = (const float*)d_in[2];
    const float* beta  = (const float*)d_in[3];
    float* out = (float*)d_out;

    cudaFuncSetAttribute(mma_kernel,
                         cudaFuncAttributeMaxDynamicSharedMemorySize, SM_TOTAL);

    prep_kernel<<<NCENT/4/256, 256>>>((const float4*)cent,
                                      (float4*)(out + 2*(size_t)N1));
    mma_kernel<<<dim3(NGX, CC), 256, SM_TOTAL>>>(x, gamma);
    pass2_kernel<<<1, 64>>>();
    pass3_kernel<<<BB/64, 256>>>(gamma, beta, out);
}

// round 6
// speedup vs baseline: 1.7790x; 1.1262x over previous
#include <cuda_runtime.h>
#include <cuda_bf16.h>
#include <cstdint>
#include <cfloat>

// Problem constants
#define BB 8192
#define CC 64
#define KK 256
#define DD 64
#define N1 (BB*CC)            // 524288
#define NCENT (CC*KK*DD)      // 1048576
#define TTILES 4
#define NGX 16                // BB / (128*TTILES)

// -------- static device scratch (no allocations allowed) --------
__device__ __align__(16) __nv_bfloat16 g_cb0[NCENT];   // h split, [c][k][d]
__device__ __align__(16) __nv_bfloat16 g_cb1[NCENT];   // m split
__device__ __align__(16) __nv_bfloat16 g_cb2[NCENT];   // l split
__device__ int    g_codei[N1];     // [c][b]
__device__ float  g_selv[N1];      // [c][b]
__device__ float2 g_part[CC*NGX];
__device__ float  g_mean[CC];
__device__ float  g_invstd[CC];

// ---------------- smem layout (dynamic) ----------------
#define SM_B      0u        // 3 splits x 32768  (256 rows x 128B, swizzled)
#define SM_A      98304u    // 2 bufs x 3 splits x 16384
#define A_BUF     49152u
#define A_SPLIT   16384u
#define SM_CAND   196608u   // 2 bufs x (128 rows x 2 warpN x float2)
#define CAND_BUF  2048u
#define SM_RED    200704u   // 8 x float2
#define SM_TOTAL  200768u

#define SWZ(o) ((uint32_t)(o) ^ ((((uint32_t)(o))>>3)&0x70u))

// ---------------- PTX helpers (portable sm_80+ only) ----------------
static __device__ __forceinline__ uint32_t smem_u32(const void* p){
    uint32_t a;
    asm("{ .reg .u64 t; cvta.to.shared.u64 t, %1; cvt.u32.u64 %0, t; }"
        : "=r"(a) : "l"(p));
    return a;
}
static __device__ __forceinline__ void ldsm4(uint32_t* r, uint32_t addr){
    asm volatile("ldmatrix.sync.aligned.m8n8.x4.shared.b16 {%0,%1,%2,%3}, [%4];"
        : "=r"(r[0]), "=r"(r[1]), "=r"(r[2]), "=r"(r[3]) : "r"(addr));
}
static __device__ __forceinline__ void mma16816(float* c, const uint32_t* a,
                                                uint32_t b0, uint32_t b1){
    asm volatile(
        "mma.sync.aligned.m16n8k16.row.col.f32.bf16.bf16.f32 "
        "{%0,%1,%2,%3}, {%4,%5,%6,%7}, {%8,%9}, {%0,%1,%2,%3};"
        : "+f"(c[0]), "+f"(c[1]), "+f"(c[2]), "+f"(c[3])
        : "r"(a[0]), "r"(a[1]), "r"(a[2]), "r"(a[3]), "r"(b0), "r"(b1));
}

// ---------------- conversion helpers ----------------
static __device__ __forceinline__ void split3(float x, __nv_bfloat16& h,
                                              __nv_bfloat16& m, __nv_bfloat16& l){
    h = __float2bfloat16_rn(x);
    float r1 = x - __bfloat162float(h);
    m = __float2bfloat16_rn(r1);
    float r2 = r1 - __bfloat162float(m);
    l = __float2bfloat16_rn(r2);
}
static __device__ __forceinline__ uint32_t pk(__nv_bfloat16 a, __nv_bfloat16 b){
    __nv_bfloat162 t = __halves2bfloat162(a, b);
    return *reinterpret_cast<uint32_t*>(&t);
}

// load one 128x64 fp32 A tile into registers (32 floats / thread)
static __device__ __forceinline__ void loadX(float4* xr, const float* __restrict__ x,
                                             int gx, int c, int t, int tid){
    const int b0 = (gx*TTILES + t)*128;
    const int q8 = tid & 7;
    #pragma unroll
    for (int i = 0; i < 4; ++i){
        int row = i*32 + (tid >> 3);
        const float4* xp = (const float4*)x + ((size_t)(b0+row)*CC + c)*(DD/4) + q8*2;
        xr[2*i]   = xp[0];
        xr[2*i+1] = xp[1];
    }
}
// convert registers -> 3 bf16 splits in smem buffer
static __device__ __forceinline__ void storeSplits(char* sm, uint32_t abase,
                                                   const float4* xr, int tid){
    const int q8 = tid & 7;
    #pragma unroll
    for (int i = 0; i < 4; ++i){
        int row = i*32 + (tid >> 3);
        float f[8] = {xr[2*i].x, xr[2*i].y, xr[2*i].z, xr[2*i].w,
                      xr[2*i+1].x, xr[2*i+1].y, xr[2*i+1].z, xr[2*i+1].w};
        uint32_t H[4], M[4], L[4];
        #pragma unroll
        for (int pi = 0; pi < 4; ++pi){
            __nv_bfloat16 h0,m0,l0,h1,m1,l1;
            split3(f[2*pi],   h0, m0, l0);
            split3(f[2*pi+1], h1, m1, l1);
            H[pi] = pk(h0,h1); M[pi] = pk(m0,m1); L[pi] = pk(l0,l1);
        }
        uint32_t so = SWZ(row*128 + q8*16);
        *(uint4*)(sm + abase + so)             = make_uint4(H[0],H[1],H[2],H[3]);
        *(uint4*)(sm + abase + A_SPLIT + so)   = make_uint4(M[0],M[1],M[2],M[3]);
        *(uint4*)(sm + abase + 2*A_SPLIT + so) = make_uint4(L[0],L[1],L[2],L[3]);
    }
}

// ---------------------------------------------------------------------------
// Main kernel: grid (NGX, CC), 256 threads, warp grid 4(m) x 2(n),
// warp tile 32x64, N in two 128-halves. 8-pass bf16 split GEMM on mma.sync.
//   sb=2 (l): {m*l, h*l}   sb=1 (m): {l*m, m*m, h*m}   sb=0 (h): {l*h, m*h, h*h}
// Pipelined: prefetch x(t+1) to regs during compute(t); single sync per tile.
// ---------------------------------------------------------------------------
__global__ __launch_bounds__(256, 1)
void mma_kernel(const float* __restrict__ x, const float* __restrict__ gamma){
    extern __shared__ __align__(16) char sm[];
    const uint32_t smb = smem_u32(sm);
    const int tid = threadIdx.x, lane = tid & 31, wid = tid >> 5;
    const int warpM = wid >> 1, warpN = wid & 1, q = lane >> 2;
    const int gx = blockIdx.x, c = blockIdx.y;

    // ---- load 3 B splits into swizzled smem (96KB) ----
    {
        const uint4* cb0 = (const uint4*)g_cb0;
        const uint4* cb1 = (const uint4*)g_cb1;
        const uint4* cb2 = (const uint4*)g_cb2;
        #pragma unroll
        for (int i = 0; i < 24; ++i){
            int flat = i*256 + tid;          // 0..6143
            int s    = flat >> 11;
            int g    = flat & 2047;
            int row  = g >> 3, q8 = g & 7;
            const uint4* src = (s==0) ? cb0 : (s==1) ? cb1 : cb2;
            uint4 v = src[((size_t)c*KK + row)*8 + q8];
            *(uint4*)(sm + SM_B + (uint32_t)s*32768u + SWZ(row*128 + q8*16)) = v;
        }
    }

    const float gmm = gamma[c];
    const bool wantMin = (gmm < 0.f);
    float sum = 0.f, sum2 = 0.f;

    // per-lane ldmatrix address components
    const uint32_t aRow  = (uint32_t)(warpM*32 + (lane & 15));
    const uint32_t aCol  = (uint32_t)((lane >> 4) << 4);       // 0 or 16 bytes
    const uint32_t bRowL = (uint32_t)(((lane >> 4) << 3) + (lane & 7));
    const uint32_t bCol  = (uint32_t)((lane & 8) << 1);        // 0 or 16 bytes

    // 8-pass tables grouped by B split (low-magnitude first within each group)
    const int SBt[3] = {2, 1, 0};
    const int SAt[3][3] = {{1,0,-1},{2,1,0},{2,1,0}};

    // prologue: load + convert tile 0
    float4 xr[8];
    loadX(xr, x, gx, c, 0, tid);
    storeSplits(sm, SM_A, xr, tid);
    __syncthreads();

    #pragma unroll 1
    for (int t = 0; t < TTILES; ++t){
        // prefetch next x tile into registers (hidden under compute)
        if (t+1 < TTILES) loadX(xr, x, gx, c, t+1, tid);

        const uint32_t abase = SM_A + (uint32_t)(t&1)*A_BUF;
        float2* cand = (float2*)(sm + SM_CAND + (uint32_t)(t&1)*CAND_BUF);

        // single-extremum running candidates per owned row-slot
        float rE[4]; int rI[4];
        #pragma unroll
        for (int s4 = 0; s4 < 4; ++s4){
            rE[s4] = wantMin ? FLT_MAX : -FLT_MAX; rI[s4] = 0;
        }

        #pragma unroll
        for (int nh = 0; nh < 2; ++nh){
            float acc[2][8][4];
            #pragma unroll
            for (int mi = 0; mi < 2; ++mi)
                #pragma unroll
                for (int nj = 0; nj < 8; ++nj)
                    #pragma unroll
                    for (int e = 0; e < 4; ++e) acc[mi][nj][e] = 0.f;

            #pragma unroll
            for (int ks = 0; ks < 4; ++ks){
                uint32_t aF[3][2][4];
                #pragma unroll
                for (int s = 0; s < 3; ++s)
                    #pragma unroll
                    for (int mi = 0; mi < 2; ++mi)
                        ldsm4(aF[s][mi], smb + abase + (uint32_t)s*16384u +
                              SWZ(aRow*128u + (uint32_t)mi*2048u +
                                  (uint32_t)ks*32u + aCol));
                #pragma unroll
                for (int g3 = 0; g3 < 3; ++g3){
                    const int sb = SBt[g3];
                    uint32_t bF[4][4];
                    #pragma unroll
                    for (int njp = 0; njp < 4; ++njp)
                        ldsm4(bF[njp], smb + SM_B + (uint32_t)sb*32768u +
                              SWZ((uint32_t)(nh*128 + warpN*64 + njp*16 + bRowL)*128u +
                                  (uint32_t)ks*32u + bCol));
                    #pragma unroll
                    for (int pi = 0; pi < 3; ++pi){
                        const int sa = SAt[g3][pi];
                        if (sa < 0) continue;
                        #pragma unroll
                        for (int mi = 0; mi < 2; ++mi)
                            #pragma unroll
                            for (int njp = 0; njp < 4; ++njp){
                                mma16816(acc[mi][2*njp],   aF[sa][mi], bF[njp][0], bF[njp][1]);
                                mma16816(acc[mi][2*njp+1], aF[sa][mi], bF[njp][2], bF[njp][3]);
                            }
                    }
                }
            }

            // ---- epilogue scan (uniform branch: track only needed extremum) ----
            const int kbase = nh*128 + warpN*64 + 2*(lane & 3);
            if (!wantMin){
                #pragma unroll
                for (int mi = 0; mi < 2; ++mi)
                    #pragma unroll
                    for (int nj = 0; nj < 8; ++nj){
                        const int k0 = kbase + nj*8;
                        float v0 = acc[mi][nj][0], v1 = acc[mi][nj][1];
                        float v2 = acc[mi][nj][2], v3 = acc[mi][nj][3];
                        sum += v0 + v1 + v2 + v3;
                        sum2 = fmaf(v0, v0, sum2); sum2 = fmaf(v1, v1, sum2);
                        sum2 = fmaf(v2, v2, sum2); sum2 = fmaf(v3, v3, sum2);
                        const int s0 = mi*2, s1 = mi*2 + 1;
                        if (v0 > rE[s0]){ rE[s0] = v0; rI[s0] = k0;   }
                        if (v1 > rE[s0]){ rE[s0] = v1; rI[s0] = k0+1; }
                        if (v2 > rE[s1]){ rE[s1] = v2; rI[s1] = k0;   }
                        if (v3 > rE[s1]){ rE[s1] = v3; rI[s1] = k0+1; }
                    }
            } else {
                #pragma unroll
                for (int mi = 0; mi < 2; ++mi)
                    #pragma unroll
                    for (int nj = 0; nj < 8; ++nj){
                        const int k0 = kbase + nj*8;
                        float v0 = acc[mi][nj][0], v1 = acc[mi][nj][1];
                        float v2 = acc[mi][nj][2], v3 = acc[mi][nj][3];
                        sum += v0 + v1 + v2 + v3;
                        sum2 = fmaf(v0, v0, sum2); sum2 = fmaf(v1, v1, sum2);
                        sum2 = fmaf(v2, v2, sum2); sum2 = fmaf(v3, v3, sum2);
                        const int s0 = mi*2, s1 = mi*2 + 1;
                        if (v0 < rE[s0]){ rE[s0] = v0; rI[s0] = k0;   }
                        if (v1 < rE[s0]){ rE[s0] = v1; rI[s0] = k0+1; }
                        if (v2 < rE[s1]){ rE[s1] = v2; rI[s1] = k0;   }
                        if (v3 < rE[s1]){ rE[s1] = v3; rI[s1] = k0+1; }
                    }
            }
        }

        // ---- cross-lane (quad) reduce, write candidates ----
        #pragma unroll
        for (int s4 = 0; s4 < 4; ++s4){
            float ev = rE[s4]; int ei = rI[s4];
            #pragma unroll
            for (int off = 1; off <= 2; off <<= 1){
                float ov = __shfl_xor_sync(0xffffffffu, ev, off);
                int   oi = __shfl_xor_sync(0xffffffffu, ei, off);
                bool take = wantMin ? (ov < ev || (ov == ev && oi < ei))
                                    : (ov > ev || (ov == ev && oi < ei));
                if (take){ ev = ov; ei = oi; }
            }
            if ((lane & 3) == 0){
                int row = warpM*32 + (s4 >> 1)*16 + (s4 & 1)*8 + q;
                cand[row*2 + warpN] = make_float2(ev, __int_as_float(ei));
            }
        }

        // convert next tile into the other A buffer (before the one sync)
        if (t+1 < TTILES)
            storeSplits(sm, SM_A + (uint32_t)((t+1)&1)*A_BUF, xr, tid);

        __syncthreads();   // covers cand(t) AND A buffer (t+1)

        // ---- merge across the two n-warps, write staged outputs ----
        if (tid < 128){
            float2 c0 = cand[tid*2 + 0], c1 = cand[tid*2 + 1];
            float ev = c0.x; int ei = __float_as_int(c0.y);
            int   oi = __float_as_int(c1.y);
            bool take = wantMin ? (c1.x < ev || (c1.x == ev && oi < ei))
                                : (c1.x > ev || (c1.x == ev && oi < ei));
            if (take){ ev = c1.x; ei = oi; }
            const int b = (gx*TTILES + t)*128 + tid;
            int code; float sv;
            if (gmm != 0.f){ code = ei; sv = ev;  }
            else           { code = 0;  sv = 0.f; }
            g_codei[(size_t)c*BB + b] = code;
            g_selv [(size_t)c*BB + b] = sv;
        }
    }

    // ---- per-block stats partial (deterministic) ----
    #pragma unroll
    for (int off = 16; off; off >>= 1){
        sum  += __shfl_xor_sync(0xffffffffu, sum,  off);
        sum2 += __shfl_xor_sync(0xffffffffu, sum2, off);
    }
    float2* red = (float2*)(sm + SM_RED);
    if (lane == 0) red[wid] = make_float2(sum, sum2);
    __syncthreads();
    if (tid == 0){
        float s = 0.f, s2 = 0.f;
        #pragma unroll
        for (int w = 0; w < 8; ++w){ s += red[w].x; s2 += red[w].y; }
        g_part[c*NGX + gx] = make_float2(s, s2);
    }
}

// ---------------------------------------------------------------------------
// Prep: centroid bf16 3-way splits + centroids passthrough to out
// ---------------------------------------------------------------------------
__global__ void prep_kernel(const float4* __restrict__ cent,
                            float4* __restrict__ outc){
    int i = blockIdx.x*256 + threadIdx.x;    // < NCENT/4
    float4 v = cent[i];
    outc[i] = v;
    float f[4] = {v.x, v.y, v.z, v.w};
    __nv_bfloat16 h[4], m[4], l[4];
    #pragma unroll
    for (int p = 0; p < 4; ++p) split3(f[p], h[p], m[p], l[p]);
    ((uint2*)g_cb0)[i] = make_uint2(pk(h[0],h[1]), pk(h[2],h[3]));
    ((uint2*)g_cb1)[i] = make_uint2(pk(m[0],m[1]), pk(m[2],m[3]));
    ((uint2*)g_cb2)[i] = make_uint2(pk(l[0],l[1]), pk(l[2],l[3]));
}

// ---------------------------------------------------------------------------
// Stats reduce: 16 partials per channel -> mean, invstd
// ---------------------------------------------------------------------------
__global__ void pass2_kernel(){
    int c = threadIdx.x;
    if (c < CC){
        double s = 0.0, s2 = 0.0;
        for (int i = 0; i < NGX; ++i){
            float2 p = g_part[c*NGX + i];
            s += (double)p.x; s2 += (double)p.y;
        }
        const double cnt = (double)BB*(double)KK;
        double mean = s / cnt;
        double var  = s2 / cnt - mean*mean;
        g_mean[c]   = (float)mean;
        g_invstd[c] = rsqrtf((float)var + 1e-5f);
    }
}

// ---------------------------------------------------------------------------
// Finalize: normalize selected values, transpose [c][b] -> [b][c], write out
// grid 512 (16 b-rows per block) for latency hiding
// ---------------------------------------------------------------------------
__global__ __launch_bounds__(256)
void pass3_kernel(const float* __restrict__ gamma, const float* __restrict__ beta,
                  float* __restrict__ out){
    __shared__ float tc[16][65];
    __shared__ float tv[16][65];
    const int tid = threadIdx.x;
    const int b0  = blockIdx.x*16;
    #pragma unroll
    for (int i = 0; i < 4; ++i){
        int flat = i*256 + tid;           // 0..1023
        int cc = flat >> 4, bq = flat & 15;
        int b  = b0 + bq;
        float g = gamma[cc];
        int  code = g_codei[(size_t)cc*BB + b];
        float val;
        if (g != 0.f)
            val = (g_selv[(size_t)cc*BB + b] - g_mean[cc])*g_invstd[cc]*g + beta[cc];
        else
            val = beta[cc];
        tc[bq][cc] = (float)code;
        tv[bq][cc] = val;
    }
    __syncthreads();
    #pragma unroll
    for (int i = 0; i < 4; ++i){
        int flat = i*256 + tid;
        int row = flat >> 6, cc = flat & 63;
        size_t o = (size_t)(b0 + row)*CC + cc;
        out[o]      = tc[row][cc];
        out[N1 + o] = tv[row][cc];
    }
}

// ---------------------------------------------------------------------------
extern "C" void kernel_launch(void* const* d_in, const int* in_sizes, int n_in,
                              void* d_out, int out_size){
    (void)in_sizes; (void)n_in; (void)out_size;
    const float* x     = (const float*)d_in[0];
    const float* cent  = (const float*)d_in[1];
    const float* gamma = (const float*)d_in[2];
    const float* beta  = (const float*)d_in[3];
    float* out = (float*)d_out;

    cudaFuncSetAttribute(mma_kernel,
                         cudaFuncAttributeMaxDynamicSharedMemorySize, SM_TOTAL);

    prep_kernel<<<NCENT/4/256, 256>>>((const float4*)cent,
                                      (float4*)(out + 2*(size_t)N1));
    mma_kernel<<<dim3(NGX, CC), 256, SM_TOTAL>>>(x, gamma);
    pass2_kernel<<<1, 64>>>();
    pass3_kernel<<<BB/16, 256>>>(gamma, beta, out);
}

// round 8
// speedup vs baseline: 2.1399x; 1.2029x over previous
#include <cuda_runtime.h>
#include <cuda_bf16.h>
#include <cstdint>
#include <cfloat>

// Problem constants
#define BB 8192
#define CC 64
#define KK 256
#define DD 64
#define N1 (BB*CC)            // 524288
#define NCENT (CC*KK*DD)      // 1048576
#define TTILES 4
#define NGX 16                // BB / (128*TTILES)

// -------- static device scratch (no allocations allowed) --------
__device__ __align__(16) __nv_bfloat16 g_cb0[NCENT];   // h split, [c][k][d]
__device__ __align__(16) __nv_bfloat16 g_cb1[NCENT];   // m split
__device__ __align__(16) __nv_bfloat16 g_cb2[NCENT];   // l split
__device__ int    g_codei[N1];     // [c][b]
__device__ float  g_selv[N1];      // [c][b]
__device__ float2 g_part[CC*NGX];
__device__ float  g_mean[CC];
__device__ float  g_invstd[CC];

// ---------------- smem layout (dynamic) ----------------
#define SM_B      0u        // 3 splits x 32768  (256 rows x 128B, swizzled)
#define SM_A      98304u    // 2 bufs x 3 splits x 16384
#define A_BUF     49152u
#define A_SPLIT   16384u
#define SM_CAND   196608u   // 2 bufs x (128 rows x 2 warpN x float2)
#define CAND_BUF  2048u
#define SM_RED    200704u   // 8 x float2
#define SM_TOTAL  200768u

#define SWZ(o) ((uint32_t)(o) ^ ((((uint32_t)(o))>>3)&0x70u))

// ---------------- PTX helpers (portable sm_80+ only) ----------------
static __device__ __forceinline__ uint32_t smem_u32(const void* p){
    uint32_t a;
    asm("{ .reg .u64 t; cvta.to.shared.u64 t, %1; cvt.u32.u64 %0, t; }"
        : "=r"(a) : "l"(p));
    return a;
}
static __device__ __forceinline__ void ldsm4(uint32_t* r, uint32_t addr){
    asm volatile("ldmatrix.sync.aligned.m8n8.x4.shared.b16 {%0,%1,%2,%3}, [%4];"
        : "=r"(r[0]), "=r"(r[1]), "=r"(r[2]), "=r"(r[3]) : "r"(addr));
}
static __device__ __forceinline__ void mma16816(float* c, const uint32_t* a,
                                                uint32_t b0, uint32_t b1){
    asm volatile(
        "mma.sync.aligned.m16n8k16.row.col.f32.bf16.bf16.f32 "
        "{%0,%1,%2,%3}, {%4,%5,%6,%7}, {%8,%9}, {%0,%1,%2,%3};"
        : "+f"(c[0]), "+f"(c[1]), "+f"(c[2]), "+f"(c[3])
        : "r"(a[0]), "r"(a[1]), "r"(a[2]), "r"(a[3]), "r"(b0), "r"(b1));
}

// ---------------- conversion helpers ----------------
static __device__ __forceinline__ void split3(float x, __nv_bfloat16& h,
                                              __nv_bfloat16& m, __nv_bfloat16& l){
    h = __float2bfloat16_rn(x);
    float r1 = x - __bfloat162float(h);
    m = __float2bfloat16_rn(r1);
    float r2 = r1 - __bfloat162float(m);
    l = __float2bfloat16_rn(r2);
}
static __device__ __forceinline__ uint32_t pk(__nv_bfloat16 a, __nv_bfloat16 b){
    __nv_bfloat162 t = __halves2bfloat162(a, b);
    return *reinterpret_cast<uint32_t*>(&t);
}

// load one 128x64 fp32 A tile into registers (32 floats / thread)
static __device__ __forceinline__ void loadX(float4* xr, const float* __restrict__ x,
                                             int gx, int c, int t, int tid){
    const int b0 = (gx*TTILES + t)*128;
    const int q8 = tid & 7;
    #pragma unroll
    for (int i = 0; i < 4; ++i){
        int row = i*32 + (tid >> 3);
        const float4* xp = (const float4*)x + ((size_t)(b0+row)*CC + c)*(DD/4) + q8*2;
        xr[2*i]   = xp[0];
        xr[2*i+1] = xp[1];
    }
}
// convert registers -> 3 bf16 splits in smem buffer
static __device__ __forceinline__ void storeSplits(char* sm, uint32_t abase,
                                                   const float4* xr, int tid){
    const int q8 = tid & 7;
    #pragma unroll
    for (int i = 0; i < 4; ++i){
        int row = i*32 + (tid >> 3);
        float f[8] = {xr[2*i].x, xr[2*i].y, xr[2*i].z, xr[2*i].w,
                      xr[2*i+1].x, xr[2*i+1].y, xr[2*i+1].z, xr[2*i+1].w};
        uint32_t H[4], M[4], L[4];
        #pragma unroll
        for (int pi = 0; pi < 4; ++pi){
            __nv_bfloat16 h0,m0,l0,h1,m1,l1;
            split3(f[2*pi],   h0, m0, l0);
            split3(f[2*pi+1], h1, m1, l1);
            H[pi] = pk(h0,h1); M[pi] = pk(m0,m1); L[pi] = pk(l0,l1);
        }
        uint32_t so = SWZ(row*128 + q8*16);
        *(uint4*)(sm + abase + so)             = make_uint4(H[0],H[1],H[2],H[3]);
        *(uint4*)(sm + abase + A_SPLIT + so)   = make_uint4(M[0],M[1],M[2],M[3]);
        *(uint4*)(sm + abase + 2*A_SPLIT + so) = make_uint4(L[0],L[1],L[2],L[3]);
    }
}

// ---------------------------------------------------------------------------
// Main kernel: grid (NGX, CC), 256 threads, warp grid 4(m) x 2(n),
// warp tile 32x64, N in two 128-halves. 6-pass bf16 split GEMM on mma.sync.
// Passes (A-split x B-split); dropped terms m*l, l*m, l*l are <= 2^-24|x||y|
// per element (~1e-8 RMS per dot), far below the top-2 gap scale:
//   sb=2 (l): {h*l}   sb=1 (m): {m*m, h*m}   sb=0 (h): {l*h, m*h, h*h}
// Pipelined: prefetch x(t+1) to regs during compute(t); single sync per tile.
// ---------------------------------------------------------------------------
__global__ __launch_bounds__(256, 1)
void mma_kernel(const float* __restrict__ x, const float* __restrict__ gamma){
    extern __shared__ __align__(16) char sm[];
    const uint32_t smb = smem_u32(sm);
    const int tid = threadIdx.x, lane = tid & 31, wid = tid >> 5;
    const int warpM = wid >> 1, warpN = wid & 1, q = lane >> 2;
    const int gx = blockIdx.x, c = blockIdx.y;

    // ---- load 3 B splits into swizzled smem (96KB) ----
    {
        const uint4* cb0 = (const uint4*)g_cb0;
        const uint4* cb1 = (const uint4*)g_cb1;
        const uint4* cb2 = (const uint4*)g_cb2;
        #pragma unroll
        for (int i = 0; i < 24; ++i){
            int flat = i*256 + tid;          // 0..6143
            int s    = flat >> 11;
            int g    = flat & 2047;
            int row  = g >> 3, q8 = g & 7;
            const uint4* src = (s==0) ? cb0 : (s==1) ? cb1 : cb2;
            uint4 v = src[((size_t)c*KK + row)*8 + q8];
            *(uint4*)(sm + SM_B + (uint32_t)s*32768u + SWZ(row*128 + q8*16)) = v;
        }
    }

    const float gmm = gamma[c];
    const bool wantMin = (gmm < 0.f);
    float sum = 0.f, sum2 = 0.f;

    // per-lane ldmatrix address components
    const uint32_t aRow  = (uint32_t)(warpM*32 + (lane & 15));
    const uint32_t aCol  = (uint32_t)((lane >> 4) << 4);       // 0 or 16 bytes
    const uint32_t bRowL = (uint32_t)(((lane >> 4) << 3) + (lane & 7));
    const uint32_t bCol  = (uint32_t)((lane & 8) << 1);        // 0 or 16 bytes

    // 6-pass tables grouped by B split (low-magnitude first within each group)
    const int SBt[3] = {2, 1, 0};
    const int SAt[3][3] = {{0,-1,-1},{1,0,-1},{2,1,0}};

    // prologue: load + convert tile 0
    float4 xr[8];
    loadX(xr, x, gx, c, 0, tid);
    storeSplits(sm, SM_A, xr, tid);
    __syncthreads();

    #pragma unroll 1
    for (int t = 0; t < TTILES; ++t){
        // prefetch next x tile into registers (hidden under compute)
        if (t+1 < TTILES) loadX(xr, x, gx, c, t+1, tid);

        const uint32_t abase = SM_A + (uint32_t)(t&1)*A_BUF;
        float2* cand = (float2*)(sm + SM_CAND + (uint32_t)(t&1)*CAND_BUF);

        // single-extremum running candidates per owned row-slot
        float rE[4]; int rI[4];
        #pragma unroll
        for (int s4 = 0; s4 < 4; ++s4){
            rE[s4] = wantMin ? FLT_MAX : -FLT_MAX; rI[s4] = 0;
        }

        #pragma unroll
        for (int nh = 0; nh < 2; ++nh){
            float acc[2][8][4];
            #pragma unroll
            for (int mi = 0; mi < 2; ++mi)
                #pragma unroll
                for (int nj = 0; nj < 8; ++nj)
                    #pragma unroll
                    for (int e = 0; e < 4; ++e) acc[mi][nj][e] = 0.f;

            #pragma unroll
            for (int ks = 0; ks < 4; ++ks){
                uint32_t aF[3][2][4];
                #pragma unroll
                for (int s = 0; s < 3; ++s)
                    #pragma unroll
                    for (int mi = 0; mi < 2; ++mi)
                        ldsm4(aF[s][mi], smb + abase + (uint32_t)s*16384u +
                              SWZ(aRow*128u + (uint32_t)mi*2048u +
                                  (uint32_t)ks*32u + aCol));
                #pragma unroll
                for (int g3 = 0; g3 < 3; ++g3){
                    const int sb = SBt[g3];
                    uint32_t bF[4][4];
                    #pragma unroll
                    for (int njp = 0; njp < 4; ++njp)
                        ldsm4(bF[njp], smb + SM_B + (uint32_t)sb*32768u +
                              SWZ((uint32_t)(nh*128 + warpN*64 + njp*16 + bRowL)*128u +
                                  (uint32_t)ks*32u + bCol));
                    #pragma unroll
                    for (int pi = 0; pi < 3; ++pi){
                        const int sa = SAt[g3][pi];
                        if (sa < 0) continue;
                        #pragma unroll
                        for (int mi = 0; mi < 2; ++mi)
                            #pragma unroll
                            for (int njp = 0; njp < 4; ++njp){
                                mma16816(acc[mi][2*njp],   aF[sa][mi], bF[njp][0], bF[njp][1]);
                                mma16816(acc[mi][2*njp+1], aF[sa][mi], bF[njp][2], bF[njp][3]);
                            }
                    }
                }
            }

            // ---- epilogue scan (uniform branch: track only needed extremum) ----
            const int kbase = nh*128 + warpN*64 + 2*(lane & 3);
            if (!wantMin){
                #pragma unroll
                for (int mi = 0; mi < 2; ++mi)
                    #pragma unroll
                    for (int nj = 0; nj < 8; ++nj){
                        const int k0 = kbase + nj*8;
                        float v0 = acc[mi][nj][0], v1 = acc[mi][nj][1];
                        float v2 = acc[mi][nj][2], v3 = acc[mi][nj][3];
                        sum += v0 + v1 + v2 + v3;
                        sum2 = fmaf(v0, v0, sum2); sum2 = fmaf(v1, v1, sum2);
                        sum2 = fmaf(v2, v2, sum2); sum2 = fmaf(v3, v3, sum2);
                        const int s0 = mi*2, s1 = mi*2 + 1;
                        if (v0 > rE[s0]){ rE[s0] = v0; rI[s0] = k0;   }
                        if (v1 > rE[s0]){ rE[s0] = v1; rI[s0] = k0+1; }
                        if (v2 > rE[s1]){ rE[s1] = v2; rI[s1] = k0;   }
                        if (v3 > rE[s1]){ rE[s1] = v3; rI[s1] = k0+1; }
                    }
            } else {
                #pragma unroll
                for (int mi = 0; mi < 2; ++mi)
                    #pragma unroll
                    for (int nj = 0; nj < 8; ++nj){
                        const int k0 = kbase + nj*8;
                        float v0 = acc[mi][nj][0], v1 = acc[mi][nj][1];
                        float v2 = acc[mi][nj][2], v3 = acc[mi][nj][3];
                        sum += v0 + v1 + v2 + v3;
                        sum2 = fmaf(v0, v0, sum2); sum2 = fmaf(v1, v1, sum2);
                        sum2 = fmaf(v2, v2, sum2); sum2 = fmaf(v3, v3, sum2);
                        const int s0 = mi*2, s1 = mi*2 + 1;
                        if (v0 < rE[s0]){ rE[s0] = v0; rI[s0] = k0;   }
                        if (v1 < rE[s0]){ rE[s0] = v1; rI[s0] = k0+1; }
                        if (v2 < rE[s1]){ rE[s1] = v2; rI[s1] = k0;   }
                        if (v3 < rE[s1]){ rE[s1] = v3; rI[s1] = k0+1; }
                    }
            }
        }

        // ---- cross-lane (quad) reduce, write candidates ----
        #pragma unroll
        for (int s4 = 0; s4 < 4; ++s4){
            float ev = rE[s4]; int ei = rI[s4];
            #pragma unroll
            for (int off = 1; off <= 2; off <<= 1){
                float ov = __shfl_xor_sync(0xffffffffu, ev, off);
                int   oi = __shfl_xor_sync(0xffffffffu, ei, off);
                bool take = wantMin ? (ov < ev || (ov == ev && oi < ei))
                                    : (ov > ev || (ov == ev && oi < ei));
                if (take){ ev = ov; ei = oi; }
            }
            if ((lane & 3) == 0){
                int row = warpM*32 + (s4 >> 1)*16 + (s4 & 1)*8 + q;
                cand[row*2 + warpN] = make_float2(ev, __int_as_float(ei));
            }
        }

        // convert next tile into the other A buffer (before the one sync)
        if (t+1 < TTILES)
            storeSplits(sm, SM_A + (uint32_t)((t+1)&1)*A_BUF, xr, tid);

        __syncthreads();   // covers cand(t) AND A buffer (t+1)

        // ---- merge across the two n-warps, write staged outputs ----
        if (tid < 128){
            float2 c0 = cand[tid*2 + 0], c1 = cand[tid*2 + 1];
            float ev = c0.x; int ei = __float_as_int(c0.y);
            int   oi = __float_as_int(c1.y);
            bool take = wantMin ? (c1.x < ev || (c1.x == ev && oi < ei))
                                : (c1.x > ev || (c1.x == ev && oi < ei));
            if (take){ ev = c1.x; ei = oi; }
            const int b = (gx*TTILES + t)*128 + tid;
            int code; float sv;
            if (gmm != 0.f){ code = ei; sv = ev;  }
            else           { code = 0;  sv = 0.f; }
            g_codei[(size_t)c*BB + b] = code;
            g_selv [(size_t)c*BB + b] = sv;
        }
    }

    // ---- per-block stats partial (deterministic) ----
    #pragma unroll
    for (int off = 16; off; off >>= 1){
        sum  += __shfl_xor_sync(0xffffffffu, sum,  off);
        sum2 += __shfl_xor_sync(0xffffffffu, sum2, off);
    }
    float2* red = (float2*)(sm + SM_RED);
    if (lane == 0) red[wid] = make_float2(sum, sum2);
    __syncthreads();
    if (tid == 0){
        float s = 0.f, s2 = 0.f;
        #pragma unroll
        for (int w = 0; w < 8; ++w){ s += red[w].x; s2 += red[w].y; }
        g_part[c*NGX + gx] = make_float2(s, s2);
    }
}

// ---------------------------------------------------------------------------
// Prep: centroid bf16 3-way splits + centroids passthrough to out
// ---------------------------------------------------------------------------
__global__ void prep_kernel(const float4* __restrict__ cent,
                            float4* __restrict__ outc){
    int i = blockIdx.x*256 + threadIdx.x;    // < NCENT/4
    float4 v = cent[i];
    outc[i] = v;
    float f[4] = {v.x, v.y, v.z, v.w};
    __nv_bfloat16 h[4], m[4], l[4];
    #pragma unroll
    for (int p = 0; p < 4; ++p) split3(f[p], h[p], m[p], l[p]);
    ((uint2*)g_cb0)[i] = make_uint2(pk(h[0],h[1]), pk(h[2],h[3]));
    ((uint2*)g_cb1)[i] = make_uint2(pk(m[0],m[1]), pk(m[2],m[3]));
    ((uint2*)g_cb2)[i] = make_uint2(pk(l[0],l[1]), pk(l[2],l[3]));
}

// ---------------------------------------------------------------------------
// Stats reduce: 16 partials per channel -> mean, invstd
// ---------------------------------------------------------------------------
__global__ void pass2_kernel(){
    int c = threadIdx.x;
    if (c < CC){
        double s = 0.0, s2 = 0.0;
        for (int i = 0; i < NGX; ++i){
            float2 p = g_part[c*NGX + i];
            s += (double)p.x; s2 += (double)p.y;
        }
        const double cnt = (double)BB*(double)KK;
        double mean = s / cnt;
        double var  = s2 / cnt - mean*mean;
        g_mean[c]   = (float)mean;
        g_invstd[c] = rsqrtf((float)var + 1e-5f);
    }
}

// ---------------------------------------------------------------------------
// Finalize: normalize selected values, transpose [c][b] -> [b][c], write out
// grid 512 (16 b-rows per block) for latency hiding
// ---------------------------------------------------------------------------
__global__ __launch_bounds__(256)
void pass3_kernel(const float* __restrict__ gamma, const float* __restrict__ beta,
                  float* __restrict__ out){
    __shared__ float tc[16][65];
    __shared__ float tv[16][65];
    const int tid = threadIdx.x;
    const int b0  = blockIdx.x*16;
    #pragma unroll
    for (int i = 0; i < 4; ++i){
        int flat = i*256 + tid;           // 0..1023
        int cc = flat >> 4, bq = flat & 15;
        int b  = b0 + bq;
        float g = gamma[cc];
        int  code = g_codei[(size_t)cc*BB + b];
        float val;
        if (g != 0.f)
            val = (g_selv[(size_t)cc*BB + b] - g_mean[cc])*g_invstd[cc]*g + beta[cc];
        else
            val = beta[cc];
        tc[bq][cc] = (float)code;
        tv[bq][cc] = val;
    }
    __syncthreads();
    #pragma unroll
    for (int i = 0; i < 4; ++i){
        int flat = i*256 + tid;
        int row = flat >> 6, cc = flat & 63;
        size_t o = (size_t)(b0 + row)*CC + cc;
        out[o]      = tc[row][cc];
        out[N1 + o] = tv[row][cc];
    }
}

// ---------------------------------------------------------------------------
extern "C" void kernel_launch(void* const* d_in, const int* in_sizes, int n_in,
                              void* d_out, int out_size){
    (void)in_sizes; (void)n_in; (void)out_size;
    const float* x     = (const float*)d_in[0];
    const float* cent  = (const float*)d_in[1];
    const float* gamma = (const float*)d_in[2];
    const float* beta  = (const float*)d_in[3];
    float* out = (float*)d_out;

    cudaFuncSetAttribute(mma_kernel,
                         cudaFuncAttributeMaxDynamicSharedMemorySize, SM_TOTAL);

    prep_kernel<<<NCENT/4/256, 256>>>((const float4*)cent,
                                      (float4*)(out + 2*(size_t)N1));
    mma_kernel<<<dim3(NGX, CC), 256, SM_TOTAL>>>(x, gamma);
    pass2_kernel<<<1, 64>>>();
    pass3_kernel<<<BB/16, 256>>>(gamma, beta, out);
}